// round 1
// baseline (speedup 1.0000x reference)
#include <cuda_runtime.h>
#include <cstdint>

// Fixed problem shape (MoeGate): x[B=4, S=4096, H=2048] fp32, weight[E=64, H=2048] fp32.
// Outputs flattened to float32: topk_idx [T*8], topk_weight [T*8], moe_loss [1].

#define HDIM 2048
#define NEXP 64
#define KTOP 8
#define BM   128     // tokens per block
#define BK   16      // k-tile
#define NTHR 128     // threads per block (16 x 8 thread tile grid, 8x8 per thread)
#define XS_LD (BM + 4)   // padded leading dims (keep 16B alignment: 132*4B = 528 = 33*16)
#define WS_LD (NEXP + 4) // 68*4B = 272 = 17*16

__device__ float g_pi[4 * NEXP];   // per (batch, expert) sum of softmax scores
__device__ float g_cnt[4 * NEXP];  // per (batch, expert) top-k counts

__global__ void zero_kernel() {
    int i = threadIdx.x;
    if (i < 4 * NEXP) { g_pi[i] = 0.f; g_cnt[i] = 0.f; }
}

__global__ __launch_bounds__(NTHR) void gate_kernel(
    const float* __restrict__ x, const float* __restrict__ w,
    float* __restrict__ out, int T, int S)
{
    // Union: GEMM tiles (xs 16x132 + ws 16x68 = 3200 floats) then logits (128x64 = 8192 floats)
    __shared__ float smem[BM * NEXP];
    float* xs = smem;                    // [BK][XS_LD]
    float* ws = smem + BK * XS_LD;       // [BK][WS_LD]
    float* logits = smem;                // reused after GEMM
    __shared__ float cnt_s[NEXP];

    const int tid = threadIdx.x;
    const int t0  = blockIdx.x * BM;
    const int ty  = tid >> 3;  // 0..15 -> m group (8 rows each)
    const int tx  = tid & 7;   // 0..7  -> n group (8 cols each)

    float acc[8][8];
#pragma unroll
    for (int i = 0; i < 8; i++)
#pragma unroll
        for (int j = 0; j < 8; j++) acc[i][j] = 0.f;

    float4 xr[4], wr[2];  // prefetch registers

    auto load_tile = [&](int kt) {
#pragma unroll
        for (int j = 0; j < 4; j++) {
            int id = tid + NTHR * j;          // 0..511
            int m = id >> 2, seg = id & 3;    // row, 16B segment
            xr[j] = *(const float4*)(x + (size_t)(t0 + m) * HDIM + kt * BK + seg * 4);
        }
#pragma unroll
        for (int j = 0; j < 2; j++) {
            int id = tid + NTHR * j;          // 0..255
            int n = id >> 2, seg = id & 3;
            wr[j] = *(const float4*)(w + (size_t)n * HDIM + kt * BK + seg * 4);
        }
    };
    auto store_tile = [&]() {
#pragma unroll
        for (int j = 0; j < 4; j++) {
            int id = tid + NTHR * j;
            int m = id >> 2, seg = id & 3;
            int kb = seg * 4;
            xs[(kb + 0) * XS_LD + m] = xr[j].x;
            xs[(kb + 1) * XS_LD + m] = xr[j].y;
            xs[(kb + 2) * XS_LD + m] = xr[j].z;
            xs[(kb + 3) * XS_LD + m] = xr[j].w;
        }
#pragma unroll
        for (int j = 0; j < 2; j++) {
            int id = tid + NTHR * j;
            int n = id >> 2, seg = id & 3;
            int kb = seg * 4;
            ws[(kb + 0) * WS_LD + n] = wr[j].x;
            ws[(kb + 1) * WS_LD + n] = wr[j].y;
            ws[(kb + 2) * WS_LD + n] = wr[j].z;
            ws[(kb + 3) * WS_LD + n] = wr[j].w;
        }
    };

    const int NK = HDIM / BK;
    load_tile(0);
    store_tile();
    __syncthreads();

    for (int kt = 0; kt < NK; kt++) {
        if (kt + 1 < NK) load_tile(kt + 1);   // global prefetch overlaps compute
#pragma unroll
        for (int k = 0; k < BK; k++) {
            const float* xrow = xs + k * XS_LD + ty * 8;
            const float* wrow = ws + k * WS_LD + tx * 8;
            float4 a0 = *(const float4*)(xrow);
            float4 a1 = *(const float4*)(xrow + 4);
            float4 b0 = *(const float4*)(wrow);
            float4 b1 = *(const float4*)(wrow + 4);
            float a[8] = {a0.x, a0.y, a0.z, a0.w, a1.x, a1.y, a1.z, a1.w};
            float b[8] = {b0.x, b0.y, b0.z, b0.w, b1.x, b1.y, b1.z, b1.w};
#pragma unroll
            for (int i = 0; i < 8; i++)
#pragma unroll
                for (int j = 0; j < 8; j++)
                    acc[i][j] = fmaf(a[i], b[j], acc[i][j]);
        }
        __syncthreads();
        if (kt + 1 < NK) {
            store_tile();
            __syncthreads();
        }
    }

    // ---- epilogue: write logits to smem (tiles no longer needed) ----
#pragma unroll
    for (int i = 0; i < 8; i++)
#pragma unroll
        for (int j = 0; j < 8; j++)
            logits[(ty * 8 + i) * NEXP + (tx * 8 + j)] = acc[i][j];
    if (tid < NEXP) cnt_s[tid] = 0.f;
    __syncthreads();

    const int warp = tid >> 5;
    const int lane = tid & 31;
    const int b = t0 / S;           // all BM tokens in one batch (S % BM == 0)
    float pi0 = 0.f, pi1 = 0.f;

    for (int i = 0; i < 32; i++) {
        int m = warp * 32 + i;      // local token
        float l0 = logits[m * NEXP + lane];
        float l1 = logits[m * NEXP + lane + 32];

        // softmax over 64 experts (lane holds experts lane, lane+32)
        float mx = fmaxf(l0, l1);
#pragma unroll
        for (int off = 16; off; off >>= 1)
            mx = fmaxf(mx, __shfl_xor_sync(0xffffffffu, mx, off));
        float e0 = __expf(l0 - mx), e1 = __expf(l1 - mx);
        float sum = e0 + e1;
#pragma unroll
        for (int off = 16; off; off >>= 1)
            sum += __shfl_xor_sync(0xffffffffu, sum, off);
        float inv = 1.f / sum;
        float s0 = e0 * inv, s1 = e1 * inv;
        pi0 += s0; pi1 += s1;

        // top-8 by iterative warp-argmax (ties -> lower index, matching lax.top_k)
        float r0 = s0, r1 = s1;
        float myw = 0.f; int myidx = 0;
#pragma unroll
        for (int j = 0; j < KTOP; j++) {
            float v; int e;
            if (r0 >= r1) { v = r0; e = lane; } else { v = r1; e = lane + 32; }
#pragma unroll
            for (int off = 16; off; off >>= 1) {
                float v2 = __shfl_xor_sync(0xffffffffu, v, off);
                int   e2 = __shfl_xor_sync(0xffffffffu, e, off);
                if (v2 > v || (v2 == v && e2 < e)) { v = v2; e = e2; }
            }
            if (lane == j) { myw = v; myidx = e; }
            if (e == lane)        r0 = -1.f;
            else if (e == lane + 32) r1 = -1.f;
            if (lane == 0) atomicAdd(&cnt_s[e], 1.f);
        }
        // sum of the 8 selected weights (lanes >= 8 contribute 0)
        float w8 = myw;
#pragma unroll
        for (int off = 16; off; off >>= 1)
            w8 += __shfl_xor_sync(0xffffffffu, w8, off);

        if (lane < KTOP) {
            size_t t = (size_t)(t0 + m);
            out[t * KTOP + lane] = (float)myidx;
            out[(size_t)T * KTOP + t * KTOP + lane] = myw / (w8 + 1e-20f);
        }
    }

    atomicAdd(&g_pi[b * NEXP + lane],      pi0);
    atomicAdd(&g_pi[b * NEXP + lane + 32], pi1);
    __syncthreads();
    if (tid < NEXP) atomicAdd(&g_cnt[b * NEXP + tid], cnt_s[tid]);
}

__global__ void loss_kernel(float* __restrict__ out, int T, int S, int B) {
    __shared__ float red[256];
    int tid = threadIdx.x;
    float v = 0.f;
    if (tid < B * NEXP) {
        float pi = g_pi[tid] / (float)S;
        float fi = g_cnt[tid] * ((float)NEXP / (float)(S * KTOP));
        v = pi * fi;
    }
    red[tid] = v;
    __syncthreads();
    for (int s = 128; s > 0; s >>= 1) {
        if (tid < s) red[tid] += red[tid + s];
        __syncthreads();
    }
    if (tid == 0)
        out[(size_t)2 * T * KTOP] = red[0] * 0.01f / (float)B;
}

extern "C" void kernel_launch(void* const* d_in, const int* in_sizes, int n_in,
                              void* d_out, int out_size)
{
    const float* x = (const float*)d_in[0];
    const float* w = (const float*)d_in[1];
    float* out = (float*)d_out;

    int Hrt = in_sizes[1] / NEXP;          // 2048
    int T   = in_sizes[0] / Hrt;           // 16384
    int B   = 4;
    int S   = T / B;                       // 4096

    zero_kernel<<<1, 256>>>();
    gate_kernel<<<T / BM, NTHR>>>(x, w, out, T, S);
    loss_kernel<<<1, 256>>>(out, T, S, B);
}

// round 6
// speedup vs baseline: 1.1349x; 1.1349x over previous
#include <cuda_runtime.h>
#include <cstdint>

// MoeGate: logits via legacy mma.sync tf32 (3xTF32 split) + exact-fp32 fixup
// for borderline tokens. Fixup uses a pure sequential-k fma chain -- the exact
// arithmetic order that matched the reference for ALL tokens in round 1.

#define HDIM   2048
#define NEXP   64
#define KTOP   8
#define BM     128
#define KC     32
#define NCHUNK (HDIM / KC)
#define NTHR   256
#define PITCH  36
#define A_FLOATS (BM * PITCH)
#define B_FLOATS (NEXP * PITCH)
#define STG_FLOATS (A_FLOATS + B_FLOATS)
#define SMEM_FLOATS (2 * STG_FLOATS)
#define LG_PITCH 65
#define NBLK   128
#define FTOK   8                 // tokens per fixup CTA iteration
#define FGRID  148

__device__ float g_pi_part[NBLK * NEXP];
__device__ float g_cnt_part[NBLK * NEXP];
__device__ int   g_flag_cnt = 0;
__device__ int   g_flag_idx[16384];

__device__ __forceinline__ void split_tf32(float v, uint32_t& hi, uint32_t& lo) {
    uint32_t u = __float_as_uint(v);
    hi = (u + 0x1000u) & 0xFFFFE000u;
    lo = __float_as_uint(v - __uint_as_float(hi));
}
__device__ __forceinline__ void mma_tf32(float* c, const uint32_t* a, const uint32_t* b) {
    asm volatile(
        "mma.sync.aligned.m16n8k8.row.col.f32.tf32.tf32.f32 "
        "{%0,%1,%2,%3}, {%4,%5,%6,%7}, {%8,%9}, {%0,%1,%2,%3};"
        : "+f"(c[0]), "+f"(c[1]), "+f"(c[2]), "+f"(c[3])
        : "r"(a[0]), "r"(a[1]), "r"(a[2]), "r"(a[3]), "r"(b[0]), "r"(b[1]));
}

__global__ __launch_bounds__(NTHR, 1) void gate_kernel(
    const float* __restrict__ x, const float* __restrict__ w,
    float* __restrict__ out, int T, int S)
{
    extern __shared__ float smem[];
    __shared__ float cnt_s[NEXP];

    const int tid  = threadIdx.x;
    const int wid  = tid >> 5;
    const int lane = tid & 31;
    const int grp  = lane >> 2;
    const int qid  = lane & 3;
    const int t0   = blockIdx.x * BM;
    const int mrow0 = (wid & 3) * 32;
    const int ncol0 = (wid >> 2) * 32;

    if (tid < NEXP) cnt_s[tid] = 0.f;

    float acc[2][4][4];
#pragma unroll
    for (int i = 0; i < 2; i++)
#pragma unroll
        for (int j = 0; j < 4; j++)
#pragma unroll
            for (int k = 0; k < 4; k++) acc[i][j][k] = 0.f;

    const float* xbase = x + (size_t)t0 * HDIM;

    float4 rx[4], rw[2];
    auto ldg_chunk = [&](int c) {
#pragma unroll
        for (int i = 0; i < 4; i++) {
            int id = tid + NTHR * i;
            rx[i] = *(const float4*)(xbase + (size_t)(id >> 3) * HDIM + c * KC + (id & 7) * 4);
        }
#pragma unroll
        for (int i = 0; i < 2; i++) {
            int id = tid + NTHR * i;
            rw[i] = *(const float4*)(w + (size_t)(id >> 3) * HDIM + c * KC + (id & 7) * 4);
        }
    };
    auto sts_chunk = [&](int st) {
        float* As = smem + st * STG_FLOATS;
        float* Bs = As + A_FLOATS;
#pragma unroll
        for (int i = 0; i < 4; i++) {
            int id = tid + NTHR * i;
            *(float4*)(As + (id >> 3) * PITCH + (id & 7) * 4) = rx[i];
        }
#pragma unroll
        for (int i = 0; i < 2; i++) {
            int id = tid + NTHR * i;
            *(float4*)(Bs + (id >> 3) * PITCH + (id & 7) * 4) = rw[i];
        }
    };

    ldg_chunk(0);

    for (int c = 0; c < NCHUNK; c++) {
        const int st = c & 1;
        sts_chunk(st);
        __syncthreads();
        if (c + 1 < NCHUNK) ldg_chunk(c + 1);

        const float* As = smem + st * STG_FLOATS;
        const float* Bs = As + A_FLOATS;

#pragma unroll
        for (int q = 0; q < KC / 8; q++) {
            const int k0 = q * 8;
            uint32_t ah[2][4], al[2][4];
#pragma unroll
            for (int mt = 0; mt < 2; mt++)
#pragma unroll
                for (int j = 0; j < 4; j++) {
                    int row = mrow0 + mt * 16 + grp + ((j & 1) << 3);
                    int col = k0 + qid + ((j >> 1) << 2);
                    split_tf32(As[row * PITCH + col], ah[mt][j], al[mt][j]);
                }
#pragma unroll
            for (int nt = 0; nt < 4; nt++) {
                int n = ncol0 + nt * 8 + grp;
                uint32_t bh[2], bl[2];
                split_tf32(Bs[n * PITCH + k0 + qid],     bh[0], bl[0]);
                split_tf32(Bs[n * PITCH + k0 + qid + 4], bh[1], bl[1]);
#pragma unroll
                for (int mt = 0; mt < 2; mt++) {
                    mma_tf32(acc[mt][nt], ah[mt], bh);
                    mma_tf32(acc[mt][nt], ah[mt], bl);
                    mma_tf32(acc[mt][nt], al[mt], bh);
                }
            }
        }
        __syncthreads();
    }

    // ---- logits -> smem ----
    float* lg = smem;
#pragma unroll
    for (int mt = 0; mt < 2; mt++)
#pragma unroll
        for (int nt = 0; nt < 4; nt++) {
            int row = mrow0 + mt * 16 + grp;
            int col = ncol0 + nt * 8 + 2 * qid;
            lg[row * LG_PITCH + col]           = acc[mt][nt][0];
            lg[row * LG_PITCH + col + 1]       = acc[mt][nt][1];
            lg[(row + 8) * LG_PITCH + col]     = acc[mt][nt][2];
            lg[(row + 8) * LG_PITCH + col + 1] = acc[mt][nt][3];
        }
    __syncthreads();

    // ---- per-token epilogue ----
    if (tid < BM) {
        float sc[NEXP];
        float mx = -1e30f;
#pragma unroll
        for (int e = 0; e < NEXP; e++) { sc[e] = lg[tid * LG_PITCH + e]; mx = fmaxf(mx, sc[e]); }
        float sum = 0.f;
#pragma unroll
        for (int e = 0; e < NEXP; e++) { sc[e] = __expf(sc[e] - mx); sum += sc[e]; }
        float inv = 1.f / sum;
#pragma unroll
        for (int e = 0; e < NEXP; e++) sc[e] *= inv;
#pragma unroll
        for (int e = 0; e < NEXP; e++) lg[tid * LG_PITCH + e] = sc[e];

        // top-9; strict > = lowest index on ties (matches lax.top_k)
        float vsel[KTOP + 1]; int isel[KTOP + 1]; float wsum = 0.f;
#pragma unroll
        for (int j = 0; j < KTOP + 1; j++) {
            float bv = -1.f; int bi = 0;
#pragma unroll
            for (int e = 0; e < NEXP; e++) if (sc[e] > bv) { bv = sc[e]; bi = e; }
            vsel[j] = bv; isel[j] = bi;
#pragma unroll
            for (int e = 0; e < NEXP; e++) if (e == bi) sc[e] = -1.f;
            if (j < KTOP) { wsum += bv; atomicAdd(&cnt_s[bi], 1.f); }
        }
        // relative gap flag: HMMA logit noise <= ~3e-5 -> 1e-3 rel gives ~30x margin
        bool flag = false;
#pragma unroll
        for (int j = 0; j < KTOP; j++)
            if (vsel[j] - vsel[j + 1] < vsel[j] * 1e-3f + 2e-6f) flag = true;

        size_t t = (size_t)t0 + tid;
        if (flag) {
            int p = atomicAdd(&g_flag_cnt, 1);
            g_flag_idx[p] = (int)t;
        }
        float rn = 1.f / (wsum + 1e-20f);
#pragma unroll
        for (int j = 0; j < KTOP; j++) {
            out[t * KTOP + j] = (float)isel[j];
            out[(size_t)T * KTOP + t * KTOP + j] = vsel[j] * rn;
        }
    }
    __syncthreads();

    if (tid < NEXP) {
        float pe = 0.f;
#pragma unroll 8
        for (int m = 0; m < BM; m++) pe += lg[m * LG_PITCH + tid];
        g_pi_part[blockIdx.x * NEXP + tid]  = pe;
        g_cnt_part[blockIdx.x * NEXP + tid] = cnt_s[tid];
    }
}

// Exact-fp32 fixup: sequential-k fma chain per (token, expert) -- identical
// arithmetic order to round-1's kernel, which matched the reference exactly.
__global__ __launch_bounds__(256) void fixup_kernel(
    const float* __restrict__ x, const float* __restrict__ w,
    float* __restrict__ out, int T)
{
    __shared__ float4 ws4[8 * 66];       // [kq][e], padded row 66
    __shared__ float4 xs4[FTOK * 9];     // [t][kq], padded row 9
    __shared__ float  lgs[FTOK][72];

    const int tid = threadIdx.x;
    const int e   = tid & 63;
    const int tp  = tid >> 6;            // 0..3 -> tokens 2tp, 2tp+1
    const int nflag = g_flag_cnt;

    for (int base = blockIdx.x * FTOK; base < nflag; base += FGRID * FTOK) {
        float acc0 = 0.f, acc1 = 0.f;

        for (int c = 0; c < 64; c++) {
            if (tid < 64) {                       // xs: 8 tok x 32 k
                int tt = tid >> 3, kq = tid & 7;
                int fi = (base + tt < nflag) ? g_flag_idx[base + tt] : g_flag_idx[base];
                xs4[tt * 9 + kq] = *(const float4*)(x + (size_t)fi * HDIM + c * 32 + kq * 4);
            }
#pragma unroll
            for (int i = 0; i < 2; i++) {         // ws: 64 e x 32 k
                int id = tid + 256 * i;
                int ee = id >> 3, kq = id & 7;
                ws4[kq * 66 + ee] = *(const float4*)(w + (size_t)ee * HDIM + c * 32 + kq * 4);
            }
            __syncthreads();
#pragma unroll
            for (int kq = 0; kq < 8; kq++) {      // k ascending: chunk-major, quad, xyzw
                float4 wv = ws4[kq * 66 + e];
                float4 x0 = xs4[(2 * tp) * 9 + kq];
                float4 x1 = xs4[(2 * tp + 1) * 9 + kq];
                acc0 = fmaf(x0.x, wv.x, acc0); acc0 = fmaf(x0.y, wv.y, acc0);
                acc0 = fmaf(x0.z, wv.z, acc0); acc0 = fmaf(x0.w, wv.w, acc0);
                acc1 = fmaf(x1.x, wv.x, acc1); acc1 = fmaf(x1.y, wv.y, acc1);
                acc1 = fmaf(x1.z, wv.z, acc1); acc1 = fmaf(x1.w, wv.w, acc1);
            }
            __syncthreads();
        }

        lgs[2 * tp][e]     = acc0;
        lgs[2 * tp + 1][e] = acc1;
        __syncthreads();

        if (tid < FTOK && base + tid < nflag) {
            int t = g_flag_idx[base + tid];
            float sc[NEXP];
            float mx = -1e30f;
#pragma unroll
            for (int j = 0; j < NEXP; j++) { sc[j] = lgs[tid][j]; mx = fmaxf(mx, sc[j]); }
            float sum = 0.f;
#pragma unroll
            for (int j = 0; j < NEXP; j++) { sc[j] = __expf(sc[j] - mx); sum += sc[j]; }
            float inv = 1.f / sum;
#pragma unroll
            for (int j = 0; j < NEXP; j++) sc[j] *= inv;

            float wsel[KTOP]; int isel[KTOP]; float wsum = 0.f;
#pragma unroll
            for (int j = 0; j < KTOP; j++) {
                float bv = -1.f; int bi = 0;
#pragma unroll
                for (int e2 = 0; e2 < NEXP; e2++) if (sc[e2] > bv) { bv = sc[e2]; bi = e2; }
                wsel[j] = bv; isel[j] = bi; wsum += bv;
                sc[bi] = -1.f;
            }
            float rn = 1.f / (wsum + 1e-20f);
#pragma unroll
            for (int j = 0; j < KTOP; j++) {
                out[(size_t)t * KTOP + j] = (float)isel[j];
                out[(size_t)T * KTOP + (size_t)t * KTOP + j] = wsel[j] * rn;
            }
        }
        __syncthreads();
    }
}

__global__ void loss_kernel(float* __restrict__ out, int T, int S, int B) {
    __shared__ float red[256];
    int tid = threadIdx.x;
    if (tid == 0) g_flag_cnt = 0;            // reset for next graph replay
    int b = tid >> 6, e = tid & 63;
    float ps = 0.f, cs = 0.f;
    int blk0 = b * (NBLK / 4);
    for (int blk = blk0; blk < blk0 + NBLK / 4; blk++) {
        ps += g_pi_part[blk * NEXP + e];
        cs += g_cnt_part[blk * NEXP + e];
    }
    float pi = ps / (float)S;
    float fi = cs * ((float)NEXP / (float)(S * KTOP));
    red[tid] = pi * fi;
    __syncthreads();
    for (int s = 128; s > 0; s >>= 1) {
        if (tid < s) red[tid] += red[tid + s];
        __syncthreads();
    }
    if (tid == 0)
        out[(size_t)2 * T * KTOP] = red[0] * 0.01f / (float)B;
}

extern "C" void kernel_launch(void* const* d_in, const int* in_sizes, int n_in,
                              void* d_out, int out_size)
{
    const float* x = (const float*)d_in[0];
    const float* w = (const float*)d_in[1];
    float* out = (float*)d_out;

    int Hrt = in_sizes[1] / NEXP;    // 2048
    int T   = in_sizes[0] / Hrt;     // 16384
    int B   = 4;
    int S   = T / B;                 // 4096

    size_t smem_bytes = SMEM_FLOATS * sizeof(float);   // 55296
    cudaFuncSetAttribute(gate_kernel, cudaFuncAttributeMaxDynamicSharedMemorySize,
                         (int)smem_bytes);

    gate_kernel<<<T / BM, NTHR, smem_bytes>>>(x, w, out, T, S);
    fixup_kernel<<<FGRID, 256>>>(x, w, out, T);
    loss_kernel<<<1, 256>>>(out, T, S, B);
}

// round 7
// speedup vs baseline: 1.3458x; 1.1859x over previous
#include <cuda_runtime.h>
#include <cstdint>

// MoeGate: logits via legacy mma.sync tf32 (3xTF32 split) + exact-fp32 fixup.
// R7: gate uses 512 threads (16 warps, 8Mx2N) for 2x latency hiding on the
// tensor pipe (R6 profile: tensor=38.9%, occ=12.4% with 8 warps); HMMA stream
// reordered for 4-apart accumulator reuse. Fixup amortizes W reads 2x.

#define HDIM   2048
#define NEXP   64
#define KTOP   8
#define BM     128
#define KC     32
#define NCHUNK (HDIM / KC)
#define NTHR   512
#define PITCH  36
#define A_FLOATS (BM * PITCH)
#define B_FLOATS (NEXP * PITCH)
#define STG_FLOATS (A_FLOATS + B_FLOATS)
#define SMEM_FLOATS (2 * STG_FLOATS)
#define LG_PITCH 65
#define NBLK   128
#define FTOK   16                // tokens per fixup CTA iteration
#define FGRID  148

__device__ float g_pi_part[NBLK * NEXP];
__device__ float g_cnt_part[NBLK * NEXP];
__device__ int   g_flag_cnt = 0;
__device__ int   g_flag_idx[16384];

__device__ __forceinline__ void split_tf32(float v, uint32_t& hi, uint32_t& lo) {
    uint32_t u = __float_as_uint(v);
    hi = (u + 0x1000u) & 0xFFFFE000u;
    lo = __float_as_uint(v - __uint_as_float(hi));
}
__device__ __forceinline__ void mma_tf32(float* c, const uint32_t* a, const uint32_t* b) {
    asm volatile(
        "mma.sync.aligned.m16n8k8.row.col.f32.tf32.tf32.f32 "
        "{%0,%1,%2,%3}, {%4,%5,%6,%7}, {%8,%9}, {%0,%1,%2,%3};"
        : "+f"(c[0]), "+f"(c[1]), "+f"(c[2]), "+f"(c[3])
        : "r"(a[0]), "r"(a[1]), "r"(a[2]), "r"(a[3]), "r"(b[0]), "r"(b[1]));
}

__global__ __launch_bounds__(NTHR, 1) void gate_kernel(
    const float* __restrict__ x, const float* __restrict__ w,
    float* __restrict__ out, int T, int S)
{
    extern __shared__ float smem[];
    __shared__ float cnt_s[NEXP];

    const int tid  = threadIdx.x;
    const int wid  = tid >> 5;
    const int lane = tid & 31;
    const int grp  = lane >> 2;
    const int qid  = lane & 3;
    const int t0   = blockIdx.x * BM;
    const int mrow0 = (wid & 7) * 16;     // 8 warps in M
    const int ncol0 = (wid >> 3) * 32;    // 2 warps in N

    if (tid < NEXP) cnt_s[tid] = 0.f;

    float acc[4][4];
#pragma unroll
    for (int j = 0; j < 4; j++)
#pragma unroll
        for (int k = 0; k < 4; k++) acc[j][k] = 0.f;

    const float* xbase = x + (size_t)t0 * HDIM;

    float4 rx[2], rw;
    auto ldg_chunk = [&](int c) {
#pragma unroll
        for (int i = 0; i < 2; i++) {
            int id = tid + NTHR * i;      // 0..1023: 128 rows x 8 segs
            rx[i] = *(const float4*)(xbase + (size_t)(id >> 3) * HDIM + c * KC + (id & 7) * 4);
        }
        rw = *(const float4*)(w + (size_t)(tid >> 3) * HDIM + c * KC + (tid & 7) * 4);
    };
    auto sts_chunk = [&](int st) {
        float* As = smem + st * STG_FLOATS;
        float* Bs = As + A_FLOATS;
#pragma unroll
        for (int i = 0; i < 2; i++) {
            int id = tid + NTHR * i;
            *(float4*)(As + (id >> 3) * PITCH + (id & 7) * 4) = rx[i];
        }
        *(float4*)(Bs + (tid >> 3) * PITCH + (tid & 7) * 4) = rw;
    };

    ldg_chunk(0);

    for (int c = 0; c < NCHUNK; c++) {
        const int st = c & 1;
        sts_chunk(st);
        __syncthreads();
        if (c + 1 < NCHUNK) ldg_chunk(c + 1);

        const float* As = smem + st * STG_FLOATS;
        const float* Bs = As + A_FLOATS;

#pragma unroll
        for (int q = 0; q < KC / 8; q++) {
            const int k0 = q * 8;
            uint32_t ah[4], al[4];
#pragma unroll
            for (int j = 0; j < 4; j++) {
                int row = mrow0 + grp + ((j & 1) << 3);
                int col = k0 + qid + ((j >> 1) << 2);
                split_tf32(As[row * PITCH + col], ah[j], al[j]);
            }
            uint32_t bh[4][2], bl[4][2];
#pragma unroll
            for (int nt = 0; nt < 4; nt++) {
                int n = ncol0 + nt * 8 + grp;
                split_tf32(Bs[n * PITCH + k0 + qid],     bh[nt][0], bl[nt][0]);
                split_tf32(Bs[n * PITCH + k0 + qid + 4], bh[nt][1], bl[nt][1]);
            }
            // hi*hi across all nt, then hi*lo, then lo*hi: dependent HMMAs on the
            // same accumulator are 4 issues apart instead of back-to-back.
#pragma unroll
            for (int nt = 0; nt < 4; nt++) mma_tf32(acc[nt], ah, bh[nt]);
#pragma unroll
            for (int nt = 0; nt < 4; nt++) mma_tf32(acc[nt], ah, bl[nt]);
#pragma unroll
            for (int nt = 0; nt < 4; nt++) mma_tf32(acc[nt], al, bh[nt]);
        }
        __syncthreads();
    }

    // ---- logits -> smem ----
    float* lg = smem;
#pragma unroll
    for (int nt = 0; nt < 4; nt++) {
        int row = mrow0 + grp;
        int col = ncol0 + nt * 8 + 2 * qid;
        lg[row * LG_PITCH + col]           = acc[nt][0];
        lg[row * LG_PITCH + col + 1]       = acc[nt][1];
        lg[(row + 8) * LG_PITCH + col]     = acc[nt][2];
        lg[(row + 8) * LG_PITCH + col + 1] = acc[nt][3];
    }
    __syncthreads();

    // ---- per-token epilogue (threads 0..127, one token each) ----
    if (tid < BM) {
        float sc[NEXP];
        float mx = -1e30f;
#pragma unroll
        for (int e = 0; e < NEXP; e++) { sc[e] = lg[tid * LG_PITCH + e]; mx = fmaxf(mx, sc[e]); }
        float sum = 0.f;
#pragma unroll
        for (int e = 0; e < NEXP; e++) { sc[e] = __expf(sc[e] - mx); sum += sc[e]; }
        float inv = 1.f / sum;
#pragma unroll
        for (int e = 0; e < NEXP; e++) sc[e] *= inv;
#pragma unroll
        for (int e = 0; e < NEXP; e++) lg[tid * LG_PITCH + e] = sc[e];

        // top-9; strict > = lowest index on ties (matches lax.top_k)
        float vsel[KTOP + 1]; int isel[KTOP + 1]; float wsum = 0.f;
#pragma unroll
        for (int j = 0; j < KTOP + 1; j++) {
            float bv = -1.f; int bi = 0;
#pragma unroll
            for (int e = 0; e < NEXP; e++) if (sc[e] > bv) { bv = sc[e]; bi = e; }
            vsel[j] = bv; isel[j] = bi;
#pragma unroll
            for (int e = 0; e < NEXP; e++) if (e == bi) sc[e] = -1.f;
            if (j < KTOP) { wsum += bv; atomicAdd(&cnt_s[bi], 1.f); }
        }
        // relative gap flag (R6-proven threshold: caught every flip)
        bool flag = false;
#pragma unroll
        for (int j = 0; j < KTOP; j++)
            if (vsel[j] - vsel[j + 1] < vsel[j] * 1e-3f + 2e-6f) flag = true;

        size_t t = (size_t)t0 + tid;
        if (flag) {
            int p = atomicAdd(&g_flag_cnt, 1);
            g_flag_idx[p] = (int)t;
        }
        float rn = 1.f / (wsum + 1e-20f);
#pragma unroll
        for (int j = 0; j < KTOP; j++) {
            out[t * KTOP + j] = (float)isel[j];
            out[(size_t)T * KTOP + t * KTOP + j] = vsel[j] * rn;
        }
    }
    __syncthreads();

    if (tid < NEXP) {
        float pe = 0.f;
#pragma unroll 8
        for (int m = 0; m < BM; m++) pe += lg[m * LG_PITCH + tid];
        g_pi_part[blockIdx.x * NEXP + tid]  = pe;
        g_cnt_part[blockIdx.x * NEXP + tid] = cnt_s[tid];
    }
}

// Exact-fp32 fixup: sequential-k fma chain per (token, expert) -- identical
// arithmetic order to round-1's kernel, which matched the reference exactly.
__global__ __launch_bounds__(256) void fixup_kernel(
    const float* __restrict__ x, const float* __restrict__ w,
    float* __restrict__ out, int T)
{
    __shared__ float4 ws4[8 * 66];        // [kq][e], padded row 66
    __shared__ float4 xs4[FTOK * 9];      // [t][kq], padded row 9
    __shared__ float  lgs[FTOK][72];

    const int tid = threadIdx.x;
    const int e   = tid & 63;
    const int tp  = tid >> 6;             // 0..3 -> tokens 4tp..4tp+3
    const int nflag = g_flag_cnt;

    for (int base = blockIdx.x * FTOK; base < nflag; base += FGRID * FTOK) {
        float acc[4] = {0.f, 0.f, 0.f, 0.f};

        for (int c = 0; c < 64; c++) {
            if (tid < 128) {              // xs: 16 tok x 32 k
                int tt = tid >> 3, kq = tid & 7;
                int fi = (base + tt < nflag) ? g_flag_idx[base + tt] : g_flag_idx[base];
                xs4[tt * 9 + kq] = *(const float4*)(x + (size_t)fi * HDIM + c * 32 + kq * 4);
            }
#pragma unroll
            for (int i = 0; i < 2; i++) { // ws: 64 e x 32 k
                int id = tid + 256 * i;
                int ee = id >> 3, kq = id & 7;
                ws4[kq * 66 + ee] = *(const float4*)(w + (size_t)ee * HDIM + c * 32 + kq * 4);
            }
            __syncthreads();
#pragma unroll
            for (int kq = 0; kq < 8; kq++) {
                float4 wv = ws4[kq * 66 + e];
#pragma unroll
                for (int u = 0; u < 4; u++) {
                    float4 xv = xs4[(4 * tp + u) * 9 + kq];
                    acc[u] = fmaf(xv.x, wv.x, acc[u]);
                    acc[u] = fmaf(xv.y, wv.y, acc[u]);
                    acc[u] = fmaf(xv.z, wv.z, acc[u]);
                    acc[u] = fmaf(xv.w, wv.w, acc[u]);
                }
            }
            __syncthreads();
        }

#pragma unroll
        for (int u = 0; u < 4; u++) lgs[4 * tp + u][e] = acc[u];
        __syncthreads();

        if (tid < FTOK && base + tid < nflag) {
            int t = g_flag_idx[base + tid];
            float sc[NEXP];
            float mx = -1e30f;
#pragma unroll
            for (int j = 0; j < NEXP; j++) { sc[j] = lgs[tid][j]; mx = fmaxf(mx, sc[j]); }
            float sum = 0.f;
#pragma unroll
            for (int j = 0; j < NEXP; j++) { sc[j] = __expf(sc[j] - mx); sum += sc[j]; }
            float inv = 1.f / sum;
#pragma unroll
            for (int j = 0; j < NEXP; j++) sc[j] *= inv;

            float wsel[KTOP]; int isel[KTOP]; float wsum = 0.f;
#pragma unroll
            for (int j = 0; j < KTOP; j++) {
                float bv = -1.f; int bi = 0;
#pragma unroll
                for (int e2 = 0; e2 < NEXP; e2++) if (sc[e2] > bv) { bv = sc[e2]; bi = e2; }
                wsel[j] = bv; isel[j] = bi; wsum += bv;
                sc[bi] = -1.f;
            }
            float rn = 1.f / (wsum + 1e-20f);
#pragma unroll
            for (int j = 0; j < KTOP; j++) {
                out[(size_t)t * KTOP + j] = (float)isel[j];
                out[(size_t)T * KTOP + (size_t)t * KTOP + j] = wsel[j] * rn;
            }
        }
        __syncthreads();
    }
}

__global__ void loss_kernel(float* __restrict__ out, int T, int S, int B) {
    __shared__ float red[256];
    int tid = threadIdx.x;
    if (tid == 0) g_flag_cnt = 0;            // reset for next graph replay
    int b = tid >> 6, e = tid & 63;
    float ps = 0.f, cs = 0.f;
    int blk0 = b * (NBLK / 4);
    for (int blk = blk0; blk < blk0 + NBLK / 4; blk++) {
        ps += g_pi_part[blk * NEXP + e];
        cs += g_cnt_part[blk * NEXP + e];
    }
    float pi = ps / (float)S;
    float fi = cs * ((float)NEXP / (float)(S * KTOP));
    red[tid] = pi * fi;
    __syncthreads();
    for (int s = 128; s > 0; s >>= 1) {
        if (tid < s) red[tid] += red[tid + s];
        __syncthreads();
    }
    if (tid == 0)
        out[(size_t)2 * T * KTOP] = red[0] * 0.01f / (float)B;
}

extern "C" void kernel_launch(void* const* d_in, const int* in_sizes, int n_in,
                              void* d_out, int out_size)
{
    const float* x = (const float*)d_in[0];
    const float* w = (const float*)d_in[1];
    float* out = (float*)d_out;

    int Hrt = in_sizes[1] / NEXP;    // 2048
    int T   = in_sizes[0] / Hrt;     // 16384
    int B   = 4;
    int S   = T / B;                 // 4096

    size_t smem_bytes = SMEM_FLOATS * sizeof(float);   // 55296
    cudaFuncSetAttribute(gate_kernel, cudaFuncAttributeMaxDynamicSharedMemorySize,
                         (int)smem_bytes);

    gate_kernel<<<T / BM, NTHR, smem_bytes>>>(x, w, out, T, S);
    fixup_kernel<<<FGRID, 256>>>(x, w, out, T);
    loss_kernel<<<1, 256>>>(out, T, S, B);
}